// round 15
// baseline (speedup 1.0000x reference)
#include <cuda_runtime.h>

#define NB 64
#define NT 512
#define NI 512
#define NH 512
#define NG 2048      // 4*H
#define GRID_R 128   // recurrent persistent CTAs (1 per SM)

// ---------------- device scratch (static: no allocs allowed) ----------------
__device__ float4 g_xbuf[(long long)NT * 128 * 64]; // [t][i4][b] quads (64 MB)
__device__ float g_hbuf[2][NH * NB];                // [k4][b][4j] packed quads
__device__ unsigned g_grp[8 * 32];                  // group counters, 128B apart
__device__ unsigned g_root[32];                     // root counter (padded line)

// ---------------- f32x2 packed-FMA helpers (Blackwell FFMA2) ----------------
__device__ __forceinline__ void fma2(unsigned long long& d,
                                     unsigned long long a,
                                     unsigned long long b) {
    asm("fma.rn.f32x2 %0, %1, %2, %0;" : "+l"(d) : "l"(a), "l"(b));
}
__device__ __forceinline__ float2 unpack2(unsigned long long v) {
    float lo, hi;
    asm("mov.b64 {%0,%1}, %2;" : "=f"(lo), "=f"(hi) : "l"(v));
    return make_float2(lo, hi);
}

// ---------------- two-level grid barrier (acq_rel atomics, replay-safe) -----
__device__ __forceinline__ unsigned bar_arrive() {
    unsigned* grp = &g_grp[(blockIdx.x & 7) << 5];
    unsigned a;
    asm volatile("atom.acq_rel.gpu.global.add.u32 %0, [%1], 1;"
                 : "=r"(a) : "l"(grp) : "memory");
    if ((a & 15u) == 15u)                    // last of 16-CTA group
        asm volatile("red.release.gpu.global.add.u32 [%0], 1;"
                     :: "l"(g_root) : "memory");
    return ((a >> 4) + 1u) * 8u;             // 8 groups per epoch
}
__device__ __forceinline__ void bar_wait(unsigned target) {
    unsigned v;
    do {
        asm volatile("ld.acquire.gpu.global.u32 %0, [%1];"
                     : "=r"(v) : "l"(g_root) : "memory");
    } while ((int)(v - target) < 0);
}

// ---------------- x transpose: x[b][t][i] -> g_xbuf[t][i4][b] quads ---------
__global__ __launch_bounds__(256) void xpose(const float* __restrict__ x) {
    __shared__ float tile[128][65];
    const int t  = blockIdx.y;
    const int i0 = blockIdx.x * 128;
    const int tid = threadIdx.x;
#pragma unroll
    for (int r = 0; r < 32; ++r) {
        int idx = r * 256 + tid;
        int b = idx >> 7, ii = idx & 127;
        tile[ii][b] = x[((long long)b * NT + t) * NI + i0 + ii];
    }
    __syncthreads();
#pragma unroll
    for (int r = 0; r < 8; ++r) {
        int idx = r * 256 + tid;
        int i4l = idx >> 6, b = idx & 63;
        float4 v = make_float4(tile[i4l * 4 + 0][b], tile[i4l * 4 + 1][b],
                               tile[i4l * 4 + 2][b], tile[i4l * 4 + 3][b]);
        g_xbuf[((long long)t * 128 + (i0 >> 2) + i4l) * 64 + b] = v;
    }
}

// ---------------- matmul phase: 8 rows x 4 b x (8 k4) per thread ------------
// lane = (g = row-half, b0 in 0..15); warp w = k-slice [w*8, w*8+8) k4.
// One broadcast W LDS.128 feeds 8 FFMA2 (4 b x 2 k-pairs).
__device__ __forceinline__ void mm_phase(const ulonglong2* __restrict__ src,
                                         const ulonglong2* __restrict__ wq,
                                         int b0, int g,
                                         unsigned long long (&acc)[8][4]) {
#pragma unroll
    for (int r = 0; r < 8; ++r)
#pragma unroll
        for (int j = 0; j < 4; ++j) acc[r][j] = 0ull;

    ulonglong2 h[2][4];
#pragma unroll
    for (int j = 0; j < 4; ++j) h[0][j] = src[b0 + j * 16];

#pragma unroll
    for (int k4 = 0; k4 < 8; ++k4) {
        const int cur = k4 & 1;
        if (k4 < 7) {
#pragma unroll
            for (int j = 0; j < 4; ++j)
                h[cur ^ 1][j] = src[(k4 + 1) * 64 + b0 + j * 16];
        }
        const ulonglong2* wr = wq + (k4 << 4) + (g << 3);
#pragma unroll
        for (int r = 0; r < 8; ++r) {
            ulonglong2 w = wr[r];                  // broadcast LDS.128
#pragma unroll
            for (int j = 0; j < 4; ++j) {
                fma2(acc[r][j], h[cur][j].x, w.x);
                fma2(acc[r][j], h[cur][j].y, w.y);
            }
        }
    }
}

// Spill acc -> red2[row16][c16][b64] (row = g*8 + r)
__device__ __forceinline__ void spill_acc(float* red2,
                                          const unsigned long long (&acc)[8][4],
                                          int w, int b0, int g) {
#pragma unroll
    for (int r = 0; r < 8; ++r) {
        const int row = (g << 3) + r;
#pragma unroll
        for (int j = 0; j < 4; ++j) {
            float2 u = unpack2(acc[r][j]);
            red2[(row << 10) + (w << 6) + b0 + j * 16] = u.x + u.y;
        }
    }
}

__device__ __forceinline__ float sum16(const float* rp) {
    float a0 = 0.f, a1 = 0.f, a2 = 0.f, a3 = 0.f;
#pragma unroll
    for (int cc = 0; cc < 16; cc += 4) {
        a0 += rp[(cc + 0) << 6]; a1 += rp[(cc + 1) << 6];
        a2 += rp[(cc + 2) << 6]; a3 += rp[(cc + 3) << 6];
    }
    return (a0 + a1) + (a2 + a3);
}

// ---------------- fused persistent kernel -----------------------------------
// CTA owns H-columns [4*bid, 4*bid+4). Per step: Phase A = h(t)·Whh + cell
// update (gates add smem xg ring); Phase B = xg(t+1) = x·Wih into the ring,
// placed BETWEEN bar_arrive and bar_wait so the grid-barrier latency is
// hidden behind its compute. No global xg tensor at all.
__global__ __launch_bounds__(512, 1) void lstm_fused(const float* __restrict__ Whh,
                                                     const float* __restrict__ Wih,
                                                     const float* __restrict__ h0,
                                                     const float* __restrict__ c0,
                                                     const float* __restrict__ bih,
                                                     const float* __restrict__ bhh,
                                                     float* __restrict__ out,
                                                     int tail) {
    extern __shared__ float smem[];
    float* wsm_hh = smem;                 // 8192 f (32 KB)
    float* wsm_ih = smem + 8192;          // 8192 f (32 KB)
    float* red2   = smem + 16384;         // 16384 f (64 KB) [row16][c16][b64]
    float* xg_s   = smem + 32768;         // 2048 f (8 KB) ring[2][16 rows][64 b]
    float* hx     = smem + 34816;         // 256 f
    float* bias_s = smem + 35072;         // 16 f

    const int tid   = threadIdx.x;
    const int b0    = tid & 15;           // lane b-base
    const int g     = (tid >> 4) & 1;     // lane row-half
    const int w     = tid >> 5;           // warp = k-slice
    const int kbase = w * 8;
    const int fin   = tid < 256;
    const int fb    = tid & 63;
    const int fj    = (tid >> 6) & 3;
    const int bid   = blockIdx.x;
    const int j0    = bid * 4;
    const int jf    = j0 + fj;

    // Stage both W slices: quad (k4*16 + row) = W[q*NH + j0+cc][4k4..4k4+3]
    for (int idx = tid; idx < 128 * 16; idx += 512) {
        int k4  = idx >> 4;
        int row = idx & 15;
        int q   = row >> 2;
        int cc  = row & 3;
        *(float4*)&wsm_hh[idx * 4] =
            *(const float4*)&Whh[(long long)(q * NH + j0 + cc) * NH + k4 * 4];
        *(float4*)&wsm_ih[idx * 4] =
            *(const float4*)&Wih[(long long)(q * NH + j0 + cc) * NI + k4 * 4];
    }
    if (tid < 16) {
        int q = tid >> 2, cc = tid & 3;
        bias_s[tid] = bih[q * NH + j0 + cc] + bhh[q * NH + j0 + cc];
    }
    // Repack h0 slice: CTA bid owns k4 = bid (256 floats: [b][4j])
    if (tid < 256)
        g_hbuf[0][bid * 256 + tid] = h0[(tid >> 2) * NH + j0 + (tid & 3)];

    float cs = fin ? c0[fb * NH + jf] : 0.f;
    int rd = 0;

    const ulonglong2* whhq = (const ulonglong2*)wsm_hh + (kbase << 4);
    const ulonglong2* wihq = (const ulonglong2*)wsm_ih + (kbase << 4);
    const ulonglong2* xb   = (const ulonglong2*)g_xbuf;

    unsigned long long acc[8][4];

    __syncthreads();                     // staging visible in-CTA
    // Prologue Phase B: xg(0) -> xg_s ring slot 0
    mm_phase(xb + (long long)kbase * 64, wihq, b0, g, acc);
    spill_acc(red2, acc, w, b0, g);
    __syncthreads();
    if (fin) {
#pragma unroll
        for (int q = 0; q < 4; ++q) {
            int row = q * 4 + fj;
            xg_s[row * 64 + fb] = sum16(&red2[(row << 10) + fb]) + bias_s[row];
        }
    }

    // initial grid barrier: h0 repack visible everywhere
    __syncthreads();
    if (tid == 0) bar_wait(bar_arrive());
    __syncthreads();

    for (int t = 0; t < NT; ++t) {
        // ---- Phase A: recurrent matmul over h(t) ----
        mm_phase((const ulonglong2*)g_hbuf[rd] + kbase * 64, whhq, b0, g, acc);
        spill_acc(red2, acc, w, b0, g);
        __syncthreads();                                   // (1)

        if (fin) {
            const float* xgt = xg_s + (t & 1) * 1024;      // bias folded in
            float gi = sum16(&red2[((0 * 4 + fj) << 10) + fb]) + xgt[(0 * 4 + fj) * 64 + fb];
            float gf = sum16(&red2[((1 * 4 + fj) << 10) + fb]) + xgt[(1 * 4 + fj) * 64 + fb];
            float gg = sum16(&red2[((2 * 4 + fj) << 10) + fb]) + xgt[(2 * 4 + fj) * 64 + fb];
            float go = sum16(&red2[((3 * 4 + fj) << 10) + fb]) + xgt[(3 * 4 + fj) * 64 + fb];

            float iv = 1.f / (1.f + __expf(-gi));
            float fv = 1.f / (1.f + __expf(-gf));
            float gv = 2.f / (1.f + __expf(-2.f * gg)) - 1.f;
            float ov = 1.f / (1.f + __expf(-go));
            cs = fv * cs + iv * gv;
            float hn = ov * (2.f / (1.f + __expf(-2.f * cs)) - 1.f);
            hx[fj * 64 + fb] = hn;
        }
        __syncthreads();                                   // (2)

        if (tid < 64) {      // float4 assemble: h exchange + output (+ h_T)
            float4 vv = make_float4(hx[tid], hx[64 + tid], hx[128 + tid], hx[192 + tid]);
            *(float4*)&g_hbuf[rd ^ 1][bid * 256 + tid * 4] = vv;
            *(float4*)&out[((long long)tid * NT + t) * NH + j0] = vv;
            if (tail && t == NT - 1)
                *(float4*)&out[(long long)NB * NT * NH + tid * NH + j0] = vv;
        }
        __syncthreads();                                   // (3) h stores done

        unsigned tg = 0;
        if (tid == 0) tg = bar_arrive();                   // publish h(t+1)

        // ---- Phase B (between arrive and wait): xg(t+1) ----
        if (t + 1 < NT) {
            mm_phase(xb + ((long long)(t + 1) * 128 + kbase) * 64, wihq, b0, g, acc);
            spill_acc(red2, acc, w, b0, g);
            __syncthreads();                               // (4)
            if (fin) {
                float* xgn = xg_s + ((t + 1) & 1) * 1024;
#pragma unroll
                for (int q = 0; q < 4; ++q) {
                    int row = q * 4 + fj;
                    xgn[row * 64 + fb] = sum16(&red2[(row << 10) + fb]) + bias_s[row];
                }
            }
        }

        if (tid == 0) bar_wait(tg);                        // mostly already done
        __syncthreads();                                   // (5)
        rd ^= 1;
    }

    if (tail && fin)
        out[(long long)NB * NT * NH + NB * NH + fb * NH + jf] = cs;   // c_T
}

// ---------------- launch ----------------
#define SMEM_BYTES (35088 * 4)

extern "C" void kernel_launch(void* const* d_in, const int* in_sizes, int n_in,
                              void* d_out, int out_size) {
    const float* x   = (const float*)d_in[0];
    const float* h0  = (const float*)d_in[1];
    const float* c0  = (const float*)d_in[2];
    const float* Wih = (const float*)d_in[3];
    const float* Whh = (const float*)d_in[4];
    const float* bih = (const float*)d_in[5];
    const float* bhh = (const float*)d_in[6];
    float* out = (float*)d_out;

    cudaFuncSetAttribute(lstm_fused, cudaFuncAttributeMaxDynamicSharedMemorySize,
                         SMEM_BYTES);
    xpose<<<dim3(4, NT), 256>>>(x);
    int tail = (out_size >= NB * NT * NH + 2 * NB * NH) ? 1 : 0;
    lstm_fused<<<GRID_R, 512, SMEM_BYTES>>>(Whh, Wih, h0, c0, bih, bhh, out, tail);
}

// round 16
// speedup vs baseline: 1.0799x; 1.0799x over previous
#include <cuda_runtime.h>

#define NB 64
#define NT 512
#define NI 512
#define NH 512
#define NG 2048      // 4*H
#define GRID_R 128   // recurrent persistent CTAs (1 per SM)

// ---------------- device scratch (static: no allocs allowed) ----------------
__device__ float4 g_xbuf[(long long)NT * 128 * 64]; // [t][i4][b] quads (64 MB)
__device__ float g_hbuf[2][NH * NB];                // [k4][b][4j] packed quads
__device__ unsigned g_grp[8 * 32];                  // group counters, 128B apart
__device__ unsigned g_root[32];                     // root counter (padded line)

// ---------------- f32x2 packed-FMA helpers (Blackwell FFMA2) ----------------
__device__ __forceinline__ void fma2(unsigned long long& d,
                                     unsigned long long a,
                                     unsigned long long b) {
    asm("fma.rn.f32x2 %0, %1, %2, %0;" : "+l"(d) : "l"(a), "l"(b));
}
__device__ __forceinline__ float2 unpack2(unsigned long long v) {
    float lo, hi;
    asm("mov.b64 {%0,%1}, %2;" : "=f"(lo), "=f"(hi) : "l"(v));
    return make_float2(lo, hi);
}

// ---------------- two-level grid barrier (acq_rel atomics, replay-safe) -----
__device__ __forceinline__ unsigned bar_arrive() {
    unsigned* grp = &g_grp[(blockIdx.x & 7) << 5];
    unsigned a;
    asm volatile("atom.acq_rel.gpu.global.add.u32 %0, [%1], 1;"
                 : "=r"(a) : "l"(grp) : "memory");
    if ((a & 15u) == 15u)                    // last of 16-CTA group
        asm volatile("red.release.gpu.global.add.u32 [%0], 1;"
                     :: "l"(g_root) : "memory");
    return ((a >> 4) + 1u) * 8u;             // 8 groups per epoch
}
__device__ __forceinline__ void bar_wait(unsigned target) {
    unsigned v;
    do {
        asm volatile("ld.acquire.gpu.global.u32 %0, [%1];"
                     : "=r"(v) : "l"(g_root) : "memory");
    } while ((int)(v - target) < 0);
}

// ---------------- x transpose: x[b][t][i] -> g_xbuf[t][i4][b] quads ---------
__global__ __launch_bounds__(256) void xpose(const float* __restrict__ x) {
    __shared__ float tile[128][65];
    const int t  = blockIdx.y;
    const int i0 = blockIdx.x * 128;
    const int tid = threadIdx.x;
#pragma unroll
    for (int r = 0; r < 32; ++r) {
        int idx = r * 256 + tid;
        int b = idx >> 7, ii = idx & 127;
        tile[ii][b] = x[((long long)b * NT + t) * NI + i0 + ii];
    }
    __syncthreads();
#pragma unroll
    for (int r = 0; r < 8; ++r) {
        int idx = r * 256 + tid;
        int i4l = idx >> 6, b = idx & 63;
        float4 v = make_float4(tile[i4l * 4 + 0][b], tile[i4l * 4 + 1][b],
                               tile[i4l * 4 + 2][b], tile[i4l * 4 + 3][b]);
        g_xbuf[((long long)t * 128 + (i0 >> 2) + i4l) * 64 + b] = v;
    }
}

// ---------------- matmul accumulate: 16 rows x (8 k4) x 2 b per thread ------
// Accumulates ONTO acc (caller zeroes). One broadcast W LDS.128 -> 4 FFMA2.
__device__ __forceinline__ void mm_acc(const ulonglong2* __restrict__ src,
                                       const ulonglong2* __restrict__ wq,
                                       int b0, unsigned long long (&acc)[16][2]) {
    ulonglong2 hra[4], hrc[4];
#pragma unroll
    for (int i = 0; i < 4; ++i) {
        hra[i] = src[i * 64 + b0];
        hrc[i] = src[i * 64 + b0 + 32];
    }
#pragma unroll
    for (int k4 = 0; k4 < 8; ++k4) {
        ulonglong2 hA = hra[k4 & 3], hB = hrc[k4 & 3];
        if (k4 < 4) {
            hra[k4] = src[(k4 + 4) * 64 + b0];
            hrc[k4] = src[(k4 + 4) * 64 + b0 + 32];
        }
        const ulonglong2* wr = wq + (k4 << 4);
#pragma unroll
        for (int r2 = 0; r2 < 16; ++r2) {
            ulonglong2 w = wr[r2];                 // broadcast LDS.128
            fma2(acc[r2][0], hA.x, w.x);
            fma2(acc[r2][0], hA.y, w.y);
            fma2(acc[r2][1], hB.x, w.x);
            fma2(acc[r2][1], hB.y, w.y);
        }
    }
}

// Spill acc -> red2[row16][c16][b64] (single pass, all 16 rows)
__device__ __forceinline__ void spill_acc(float* red2,
                                          const unsigned long long (&acc)[16][2],
                                          int c, int b0) {
#pragma unroll
    for (int r2 = 0; r2 < 16; ++r2) {
        float2 u0 = unpack2(acc[r2][0]);
        float2 u1 = unpack2(acc[r2][1]);
        red2[(r2 << 10) + (c << 6) + b0]      = u0.x + u0.y;
        red2[(r2 << 10) + (c << 6) + b0 + 32] = u1.x + u1.y;
    }
}

__device__ __forceinline__ float sum16(const float* rp) {
    float a0 = 0.f, a1 = 0.f, a2 = 0.f, a3 = 0.f;
#pragma unroll
    for (int cc = 0; cc < 16; cc += 4) {
        a0 += rp[(cc + 0) << 6]; a1 += rp[(cc + 1) << 6];
        a2 += rp[(cc + 2) << 6]; a3 += rp[(cc + 3) << 6];
    }
    return (a0 + a1) + (a2 + a3);
}

// ---------------- fused persistent kernel -----------------------------------
// CTA owns H-columns [4*bid, 4*bid+4). gates = [h(t); x(t)]·[Whh; Wih]^T:
// x-partials are accumulated into acc during the PREVIOUS step's barrier
// window (h-independent -> hides barrier latency); h-partials accumulate onto
// the same registers at the top of the step. ONE spill + ONE reduction ladder.
__global__ __launch_bounds__(512, 1) void lstm_fused(const float* __restrict__ Whh,
                                                     const float* __restrict__ Wih,
                                                     const float* __restrict__ h0,
                                                     const float* __restrict__ c0,
                                                     const float* __restrict__ bih,
                                                     const float* __restrict__ bhh,
                                                     float* __restrict__ out,
                                                     int tail) {
    extern __shared__ float smem[];
    float* wsm_hh = smem;                 // 8192 f (32 KB)
    float* wsm_ih = smem + 8192;          // 8192 f (32 KB)
    float* red2   = smem + 16384;         // 16384 f (64 KB) [row16][c16][b64]
    float* hx     = smem + 32768;         // 256 f
    float* bias_s = smem + 33024;         // 16 f

    const int tid   = threadIdx.x;
    const int b0    = tid & 31;
    const int c     = tid >> 5;           // warp = k-slice
    const int kbase = c * 8;
    const int fin   = tid < 256;
    const int fb    = tid & 63;
    const int fj    = (tid >> 6) & 3;
    const int bid   = blockIdx.x;
    const int j0    = bid * 4;
    const int jf    = j0 + fj;

    // Stage both W slices: quad (k4*16 + row) = W[q*NH + j0+cc][4k4..4k4+3]
    for (int idx = tid; idx < 128 * 16; idx += 512) {
        int k4  = idx >> 4;
        int row = idx & 15;
        int q   = row >> 2;
        int cc  = row & 3;
        *(float4*)&wsm_hh[idx * 4] =
            *(const float4*)&Whh[(long long)(q * NH + j0 + cc) * NH + k4 * 4];
        *(float4*)&wsm_ih[idx * 4] =
            *(const float4*)&Wih[(long long)(q * NH + j0 + cc) * NI + k4 * 4];
    }
    if (tid < 16) {
        int q = tid >> 2, cc = tid & 3;
        bias_s[tid] = bih[q * NH + j0 + cc] + bhh[q * NH + j0 + cc];
    }
    // Repack h0 slice: CTA bid owns k4 = bid (256 floats: [b][4j])
    if (tid < 256)
        g_hbuf[0][bid * 256 + tid] = h0[(tid >> 2) * NH + j0 + (tid & 3)];

    float cs = fin ? c0[fb * NH + jf] : 0.f;
    int rd = 0;

    const ulonglong2* whhq = (const ulonglong2*)wsm_hh + (kbase << 4);
    const ulonglong2* wihq = (const ulonglong2*)wsm_ih + (kbase << 4);
    const ulonglong2* xb   = (const ulonglong2*)g_xbuf;

    unsigned long long acc[16][2];

    __syncthreads();                     // staging visible in-CTA
    // Prologue: acc = x(0)·Wih partials
#pragma unroll
    for (int r2 = 0; r2 < 16; ++r2) { acc[r2][0] = 0ull; acc[r2][1] = 0ull; }
    mm_acc(xb + (long long)kbase * 64, wihq, b0, acc);

    // initial grid barrier: h0 repack visible everywhere
    __syncthreads();
    if (tid == 0) bar_wait(bar_arrive());
    __syncthreads();

    for (int t = 0; t < NT; ++t) {
        // ---- h(t)·Whh accumulates onto the x partials already in acc ----
        mm_acc((const ulonglong2*)g_hbuf[rd] + kbase * 64, whhq, b0, acc);
        spill_acc(red2, acc, c, b0);
        __syncthreads();                                   // (1)

        if (fin) {
            float gi = sum16(&red2[((0 * 4 + fj) << 10) + fb]) + bias_s[0 * 4 + fj];
            float gf = sum16(&red2[((1 * 4 + fj) << 10) + fb]) + bias_s[1 * 4 + fj];
            float gg = sum16(&red2[((2 * 4 + fj) << 10) + fb]) + bias_s[2 * 4 + fj];
            float go = sum16(&red2[((3 * 4 + fj) << 10) + fb]) + bias_s[3 * 4 + fj];

            float iv = 1.f / (1.f + __expf(-gi));
            float fv = 1.f / (1.f + __expf(-gf));
            float gv = 2.f / (1.f + __expf(-2.f * gg)) - 1.f;
            float ov = 1.f / (1.f + __expf(-go));
            cs = fv * cs + iv * gv;
            float hn = ov * (2.f / (1.f + __expf(-2.f * cs)) - 1.f);
            hx[fj * 64 + fb] = hn;
        }
        __syncthreads();                                   // (2)

        if (tid < 64) {      // float4 assemble: h exchange + output (+ h_T)
            float4 vv = make_float4(hx[tid], hx[64 + tid], hx[128 + tid], hx[192 + tid]);
            *(float4*)&g_hbuf[rd ^ 1][bid * 256 + tid * 4] = vv;
            *(float4*)&out[((long long)tid * NT + t) * NH + j0] = vv;
            if (tail && t == NT - 1)
                *(float4*)&out[(long long)NB * NT * NH + tid * NH + j0] = vv;
        }
        __syncthreads();                                   // (3) h stores done

        unsigned tg = 0;
        if (tid == 0) tg = bar_arrive();                   // publish h(t+1)

        // ---- barrier window: acc = x(t+1)·Wih partials (h-independent) ----
#pragma unroll
        for (int r2 = 0; r2 < 16; ++r2) { acc[r2][0] = 0ull; acc[r2][1] = 0ull; }
        if (t + 1 < NT)
            mm_acc(xb + ((long long)(t + 1) * 128 + kbase) * 64, wihq, b0, acc);

        if (tid == 0) bar_wait(tg);                        // mostly already done
        __syncthreads();                                   // (4)
        rd ^= 1;
    }

    if (tail && fin)
        out[(long long)NB * NT * NH + NB * NH + fb * NH + jf] = cs;   // c_T
}

// ---------------- launch ----------------
#define SMEM_BYTES (33040 * 4)

extern "C" void kernel_launch(void* const* d_in, const int* in_sizes, int n_in,
                              void* d_out, int out_size) {
    const float* x   = (const float*)d_in[0];
    const float* h0  = (const float*)d_in[1];
    const float* c0  = (const float*)d_in[2];
    const float* Wih = (const float*)d_in[3];
    const float* Whh = (const float*)d_in[4];
    const float* bih = (const float*)d_in[5];
    const float* bhh = (const float*)d_in[6];
    float* out = (float*)d_out;

    cudaFuncSetAttribute(lstm_fused, cudaFuncAttributeMaxDynamicSharedMemorySize,
                         SMEM_BYTES);
    xpose<<<dim3(4, NT), 256>>>(x);
    int tail = (out_size >= NB * NT * NH + 2 * NB * NH) ? 1 : 0;
    lstm_fused<<<GRID_R, 512, SMEM_BYTES>>>(Whh, Wih, h0, c0, bih, bhh, out, tail);
}